// round 3
// baseline (speedup 1.0000x reference)
#include <cuda_runtime.h>
#include <cstdint>

#define NN 100000
#define EE 1600000
#define DD 128
#define HH 128

// Scratch: per-relation weighted neighbor sums (float4-typed => 16B aligned)
// and in-degree counts.
__device__ float4 g_s4[3][NN][DD / 4];   // 153.6 MB
__device__ float  g_deg[3][NN];

// ---------------------------------------------------------------------------
// Zeroing kernels (must run every launch: graph replays require determinism)
// ---------------------------------------------------------------------------
__global__ void zero_s_kernel() {
    size_t i = (size_t)blockIdx.x * blockDim.x + threadIdx.x;
    size_t total = (size_t)3 * NN * (DD / 4);
    if (i < total) ((float4*)g_s4)[i] = make_float4(0.f, 0.f, 0.f, 0.f);
}
__global__ void zero_deg_kernel() {
    int i = blockIdx.x * blockDim.x + threadIdx.x;
    if (i < 3 * NN) ((float*)g_deg)[i] = 0.f;
}

// ---------------------------------------------------------------------------
// Edge scatter: one warp per edge. Gather x[src] (32 lanes x float4 = 512B),
// scale by w, float4 atomicAdd into s[r][dst]. Lane 0 counts degree.
// ---------------------------------------------------------------------------
__global__ void edge_kernel(
    const float* __restrict__ x,
    const int* __restrict__ src0, const int* __restrict__ dst0, const float* __restrict__ w0,
    const int* __restrict__ src1, const int* __restrict__ dst1, const float* __restrict__ w1,
    const int* __restrict__ src2, const int* __restrict__ dst2, const float* __restrict__ w2)
{
    int e = (int)((blockIdx.x * blockDim.x + threadIdx.x) >> 5);
    if (e >= EE) return;
    int lane = threadIdx.x & 31;
    int r = blockIdx.y;

    const int*   src = (r == 0) ? src0 : ((r == 1) ? src1 : src2);
    const int*   dst = (r == 0) ? dst0 : ((r == 1) ? dst1 : dst2);
    const float* w   = (r == 0) ? w0   : ((r == 1) ? w1   : w2);

    int   u  = __ldg(&src[e]);
    int   v  = __ldg(&dst[e]);
    float ww = __ldg(&w[e]);

    float4 xv = ((const float4*)x)[(size_t)u * 32 + lane];
    float4 m  = make_float4(xv.x * ww, xv.y * ww, xv.z * ww, xv.w * ww);

    atomicAdd(&g_s4[r][v][lane], m);          // RED.E.ADD.F32x4 (sm_90+), 16B aligned

    if (lane == 0) atomicAdd(&g_deg[r][v], 1.0f);
}

// ---------------------------------------------------------------------------
// Packed f32x2 helpers (ptxas will not auto-fuse FFMA2 from C++).
// b64 ("l") constraints matching the verified ptx_helpers pattern.
// ---------------------------------------------------------------------------
__device__ __forceinline__ uint64_t pack2(float lo, float hi) {
    uint64_t d;
    asm("mov.b64 %0, {%1, %2};" : "=l"(d) : "f"(lo), "f"(hi));
    return d;
}
__device__ __forceinline__ uint64_t fma2(uint64_t a, uint64_t b, uint64_t c) {
    uint64_t d;
    asm("fma.rn.f32x2 %0, %1, %2, %3;" : "=l"(d) : "l"(a), "l"(b), "l"(c));
    return d;
}
__device__ __forceinline__ void unpack2(uint64_t d, float& lo, float& hi) {
    asm("mov.b64 {%0, %1}, %2;" : "=f"(lo), "=f"(hi) : "l"(d));
}

// ---------------------------------------------------------------------------
// Fused GEMM + epilogue.
// Per relation r:  z = [x | s_r * invdeg_r] @ [Wself_r ; Wneigh_r] + b_r
// (a single K=256 GEMM), then out += relu(z).  Finally out /= 3.
// Block: 128 rows (nodes) x 128 cols (H), 256 threads, 8x8 per thread,
// K-tiles of 16, packed f32x2 accumulation (8 x 4 b64 accumulators).
// ---------------------------------------------------------------------------
__global__ __launch_bounds__(256) void gemm_kernel(
    const float* __restrict__ x,
    const float* __restrict__ Ws0, const float* __restrict__ Wn0, const float* __restrict__ b0,
    const float* __restrict__ Ws1, const float* __restrict__ Wn1, const float* __restrict__ b1,
    const float* __restrict__ Ws2, const float* __restrict__ Wn2, const float* __restrict__ b2,
    float* __restrict__ out)
{
    __shared__ __align__(16) float As[16][132];
    __shared__ __align__(16) float Bs[16][132];
    __shared__ float sdeg[3][128];

    int t  = threadIdx.x;
    int m0 = blockIdx.x * 128;

    if (t < 128) {
        #pragma unroll
        for (int r = 0; r < 3; r++) {
            int m = m0 + t;
            sdeg[r][t] = (m < NN) ? (1.0f / fmaxf(g_deg[r][m], 1.0f)) : 0.0f;
        }
    }
    __syncthreads();

    int tx = t & 15;    // col group: cols tx*8 .. tx*8+7
    int ty = t >> 4;    // row group: rows ty*8 .. ty*8+7

    const float* WsArr[3] = {Ws0, Ws1, Ws2};
    const float* WnArr[3] = {Wn0, Wn1, Wn2};
    const float* bArr[3]  = {b0, b1, b2};

    float oacc[8][8];
    #pragma unroll
    for (int i = 0; i < 8; i++)
        #pragma unroll
        for (int j = 0; j < 8; j++) oacc[i][j] = 0.f;

    for (int r = 0; r < 3; r++) {
        uint64_t z[8][4];
        #pragma unroll
        for (int i = 0; i < 8; i++)
            #pragma unroll
            for (int j = 0; j < 4; j++) z[i][j] = 0ull;   // == {0.f, 0.f}

        const float* Wsr    = WsArr[r];
        const float* Wnr    = WnArr[r];
        const float* srBase = (const float*)&g_s4[r][0][0];

        for (int kt = 0; kt < 16; kt++) {
            // ---- load A tile (transposed into shared): 128 rows x 16 k
            #pragma unroll
            for (int h = 0; h < 2; h++) {
                int f   = t + h * 256;
                int row = f >> 2;
                int kq  = f & 3;
                int k   = kt * 16 + kq * 4;
                int m   = m0 + row;
                float4 v = make_float4(0.f, 0.f, 0.f, 0.f);
                if (m < NN) {
                    if (k < 128) {
                        v = *(const float4*)(x + (size_t)m * 128 + k);
                    } else {
                        v = *(const float4*)(srBase + (size_t)m * 128 + (k - 128));
                        float iv = sdeg[r][row];
                        v.x *= iv; v.y *= iv; v.z *= iv; v.w *= iv;
                    }
                }
                As[kq * 4 + 0][row] = v.x;
                As[kq * 4 + 1][row] = v.y;
                As[kq * 4 + 2][row] = v.z;
                As[kq * 4 + 3][row] = v.w;
            }
            // ---- load B tile: 16 k x 128 cols
            #pragma unroll
            for (int h = 0; h < 2; h++) {
                int f  = t + h * 256;
                int kk = f >> 5;
                int cq = f & 31;
                int k  = kt * 16 + kk;
                float4 v;
                if (k < 128) v = *(const float4*)(Wsr + (size_t)k * 128 + cq * 4);
                else         v = *(const float4*)(Wnr + (size_t)(k - 128) * 128 + cq * 4);
                *(float4*)&Bs[kk][cq * 4] = v;
            }
            __syncthreads();

            #pragma unroll
            for (int kk = 0; kk < 16; kk++) {
                float a[8];
                *(float4*)&a[0] = *(const float4*)&As[kk][ty * 8];
                *(float4*)&a[4] = *(const float4*)&As[kk][ty * 8 + 4];
                uint64_t bp[4];
                const uint64_t* bsp = (const uint64_t*)&Bs[kk][tx * 8];
                bp[0] = bsp[0]; bp[1] = bsp[1]; bp[2] = bsp[2]; bp[3] = bsp[3];
                #pragma unroll
                for (int i = 0; i < 8; i++) {
                    uint64_t a2 = pack2(a[i], a[i]);
                    #pragma unroll
                    for (int j = 0; j < 4; j++)
                        z[i][j] = fma2(a2, bp[j], z[i][j]);
                }
            }
            __syncthreads();
        }

        // ---- relation epilogue: bias + relu, accumulate
        float bv[8];
        #pragma unroll
        for (int j = 0; j < 8; j++) bv[j] = __ldg(&bArr[r][tx * 8 + j]);
        #pragma unroll
        for (int i = 0; i < 8; i++) {
            #pragma unroll
            for (int j2 = 0; j2 < 4; j2++) {
                float lo, hi;
                unpack2(z[i][j2], lo, hi);
                oacc[i][2 * j2 + 0] += fmaxf(lo + bv[2 * j2 + 0], 0.f);
                oacc[i][2 * j2 + 1] += fmaxf(hi + bv[2 * j2 + 1], 0.f);
            }
        }
    }

    // ---- write output: mean over 3 relations
    const float third = 1.0f / 3.0f;
    #pragma unroll
    for (int i = 0; i < 8; i++) {
        int m = m0 + ty * 8 + i;
        if (m < NN) {
            float4 o0 = make_float4(oacc[i][0] * third, oacc[i][1] * third,
                                    oacc[i][2] * third, oacc[i][3] * third);
            float4 o1 = make_float4(oacc[i][4] * third, oacc[i][5] * third,
                                    oacc[i][6] * third, oacc[i][7] * third);
            *(float4*)(out + (size_t)m * 128 + tx * 8)     = o0;
            *(float4*)(out + (size_t)m * 128 + tx * 8 + 4) = o1;
        }
    }
}

// ---------------------------------------------------------------------------
// Launch. Inputs are identified BY SIZE, not by position, so both possible
// metadata orderings (reference-signature order or setup_inputs dict order)
// resolve correctly:
//   size 12,800,000 -> x
//   size  1,600,000 -> edge arrays, appearing as (src, dst, w) triplets
//                      per relation in both orderings
//   size     16,384 -> weight matrices, (Wself, Wneigh) pairs per relation
//   size        128 -> biases, one per relation in order
// ---------------------------------------------------------------------------
extern "C" void kernel_launch(void* const* d_in, const int* in_sizes, int n_in,
                              void* d_out, int out_size)
{
    const float* x = nullptr;
    const int*   srcA[3] = {nullptr, nullptr, nullptr};
    const int*   dstA[3] = {nullptr, nullptr, nullptr};
    const float* wA[3]   = {nullptr, nullptr, nullptr};
    const float* WsA[3]  = {nullptr, nullptr, nullptr};
    const float* WnA[3]  = {nullptr, nullptr, nullptr};
    const float* bA[3]   = {nullptr, nullptr, nullptr};

    int nEdge = 0, nMat = 0, nBias = 0;
    for (int i = 0; i < n_in; i++) {
        int sz = in_sizes[i];
        if (sz == NN * DD) {
            x = (const float*)d_in[i];
        } else if (sz == EE) {
            int k = nEdge++;
            int rel = k / 3, kind = k % 3;
            if (rel < 3) {
                if (kind == 0)      srcA[rel] = (const int*)d_in[i];
                else if (kind == 1) dstA[rel] = (const int*)d_in[i];
                else                wA[rel]   = (const float*)d_in[i];
            }
        } else if (sz == DD * HH) {
            int k = nMat++;
            int rel = k / 2;
            if (rel < 3) {
                if ((k & 1) == 0) WsA[rel] = (const float*)d_in[i];
                else              WnA[rel] = (const float*)d_in[i];
            }
        } else if (sz == HH) {
            if (nBias < 3) bA[nBias++] = (const float*)d_in[i];
        }
    }

    float* out = (float*)d_out;

    // 1) zero scratch
    {
        size_t total4 = (size_t)3 * NN * (DD / 4);        // 9.6M float4
        int blocks = (int)((total4 + 255) / 256);
        zero_s_kernel<<<blocks, 256>>>();
        zero_deg_kernel<<<(3 * NN + 255) / 256, 256>>>();
    }

    // 2) edge aggregation: warp per edge, 8 edges per 256-thread block
    {
        dim3 grid((EE + 7) / 8, 3);
        edge_kernel<<<grid, 256>>>(x,
            srcA[0], dstA[0], wA[0],
            srcA[1], dstA[1], wA[1],
            srcA[2], dstA[2], wA[2]);
    }

    // 3) fused GEMM + epilogue
    {
        int blocks = (NN + 127) / 128;   // 782
        gemm_kernel<<<blocks, 256>>>(x,
            WsA[0], WnA[0], bA[0],
            WsA[1], WnA[1], bA[1],
            WsA[2], WnA[2], bA[2], out);
    }
}

// round 4
// speedup vs baseline: 1.2522x; 1.2522x over previous
#include <cuda_runtime.h>
#include <cstdint>

#define NN 100000
#define EE 1600000
#define DD 128
#define HH 128

// Single-relation scratch (51.2 MB): stays L2-resident together with x (51.2 MB).
__device__ float4 g_s4[NN][DD / 4];
__device__ float  g_deg[NN];

// ---------------------------------------------------------------------------
// Zero scratch (s + deg in one kernel)
// ---------------------------------------------------------------------------
__global__ void zero_kernel() {
    int i = blockIdx.x * blockDim.x + threadIdx.x;
    int total4 = NN * (DD / 4);                  // 3.2M float4
    if (i < total4) ((float4*)g_s4)[i] = make_float4(0.f, 0.f, 0.f, 0.f);
    if (i < NN) g_deg[i] = 0.f;
}

// ---------------------------------------------------------------------------
// Edge scatter for ONE relation: warp per edge. Gather x[src] (32 lanes x
// float4 = 512B), scale by w, f32x4 atomicAdd into s[dst] (L2-resident).
// ---------------------------------------------------------------------------
__global__ void edge_kernel(
    const float* __restrict__ x,
    const int* __restrict__ src, const int* __restrict__ dst,
    const float* __restrict__ w)
{
    int e = (int)((blockIdx.x * blockDim.x + threadIdx.x) >> 5);
    if (e >= EE) return;
    int lane = threadIdx.x & 31;

    int   u  = __ldg(&src[e]);
    int   v  = __ldg(&dst[e]);
    float ww = __ldg(&w[e]);

    float4 xv = ((const float4*)x)[(size_t)u * 32 + lane];
    float4 m  = make_float4(xv.x * ww, xv.y * ww, xv.z * ww, xv.w * ww);

    atomicAdd(&g_s4[v][lane], m);                 // RED.E.ADD.F32x4

    if (lane == 0) atomicAdd(&g_deg[v], 1.0f);
}

// ---------------------------------------------------------------------------
// Packed f32x2 helpers
// ---------------------------------------------------------------------------
__device__ __forceinline__ uint64_t pack2(float lo, float hi) {
    uint64_t d;
    asm("mov.b64 %0, {%1, %2};" : "=l"(d) : "f"(lo), "f"(hi));
    return d;
}
__device__ __forceinline__ uint64_t fma2(uint64_t a, uint64_t b, uint64_t c) {
    uint64_t d;
    asm("fma.rn.f32x2 %0, %1, %2, %3;" : "=l"(d) : "l"(a), "l"(b), "l"(c));
    return d;
}
__device__ __forceinline__ void unpack2(uint64_t d, float& lo, float& hi) {
    asm("mov.b64 {%0, %1}, %2;" : "=f"(lo), "=f"(hi) : "l"(d));
}

// ---------------------------------------------------------------------------
// GEMM for ONE relation:
//   z = [x | s*invdeg] @ [Wself ; Wneigh] + b      (K=256)
//   out (+)= relu(z) / 3
// Block 128x128, 256 threads, 8x8/thread, f32x2 accumulation only (64 regs).
// __launch_bounds__(256,2) -> <=128 regs -> 2 CTAs/SM.
// ---------------------------------------------------------------------------
__global__ __launch_bounds__(256, 2) void gemm_kernel(
    const float* __restrict__ x,
    const float* __restrict__ Ws, const float* __restrict__ Wn,
    const float* __restrict__ b,
    float* __restrict__ out, int first)
{
    __shared__ __align__(16) float As[16][132];
    __shared__ __align__(16) float Bs[16][132];
    __shared__ float sdeg[128];

    int t  = threadIdx.x;
    int m0 = blockIdx.x * 128;

    if (t < 128) {
        int m = m0 + t;
        sdeg[t] = (m < NN) ? (1.0f / fmaxf(g_deg[m], 1.0f)) : 0.0f;
    }
    __syncthreads();

    int tx = t & 15;    // col group: cols tx*8 .. tx*8+7
    int ty = t >> 4;    // row group: rows ty*8 .. ty*8+7

    uint64_t z[8][4];
    #pragma unroll
    for (int i = 0; i < 8; i++)
        #pragma unroll
        for (int j = 0; j < 4; j++) z[i][j] = 0ull;   // == {0.f, 0.f}

    const float* srBase = (const float*)&g_s4[0][0];

    for (int kt = 0; kt < 16; kt++) {
        // ---- load A tile (transposed into shared): 128 rows x 16 k
        #pragma unroll
        for (int h = 0; h < 2; h++) {
            int f   = t + h * 256;
            int row = f >> 2;
            int kq  = f & 3;
            int k   = kt * 16 + kq * 4;
            int m   = m0 + row;
            float4 v = make_float4(0.f, 0.f, 0.f, 0.f);
            if (m < NN) {
                if (k < 128) {
                    v = *(const float4*)(x + (size_t)m * 128 + k);
                } else {
                    v = *(const float4*)(srBase + (size_t)m * 128 + (k - 128));
                    float iv = sdeg[row];
                    v.x *= iv; v.y *= iv; v.z *= iv; v.w *= iv;
                }
            }
            As[kq * 4 + 0][row] = v.x;
            As[kq * 4 + 1][row] = v.y;
            As[kq * 4 + 2][row] = v.z;
            As[kq * 4 + 3][row] = v.w;
        }
        // ---- load B tile: 16 k x 128 cols
        #pragma unroll
        for (int h = 0; h < 2; h++) {
            int f  = t + h * 256;
            int kk = f >> 5;
            int cq = f & 31;
            int k  = kt * 16 + kk;
            float4 v;
            if (k < 128) v = *(const float4*)(Ws + (size_t)k * 128 + cq * 4);
            else         v = *(const float4*)(Wn + (size_t)(k - 128) * 128 + cq * 4);
            *(float4*)&Bs[kk][cq * 4] = v;
        }
        __syncthreads();

        #pragma unroll
        for (int kk = 0; kk < 16; kk++) {
            float a[8];
            *(float4*)&a[0] = *(const float4*)&As[kk][ty * 8];
            *(float4*)&a[4] = *(const float4*)&As[kk][ty * 8 + 4];
            uint64_t bp[4];
            const uint64_t* bsp = (const uint64_t*)&Bs[kk][tx * 8];
            bp[0] = bsp[0]; bp[1] = bsp[1]; bp[2] = bsp[2]; bp[3] = bsp[3];
            #pragma unroll
            for (int i = 0; i < 8; i++) {
                uint64_t a2 = pack2(a[i], a[i]);
                #pragma unroll
                for (int j = 0; j < 4; j++)
                    z[i][j] = fma2(a2, bp[j], z[i][j]);
            }
        }
        __syncthreads();
    }

    // ---- epilogue: bias + relu, scale 1/3, accumulate into out
    const float third = 1.0f / 3.0f;
    float bv[8];
    #pragma unroll
    for (int j = 0; j < 8; j++) bv[j] = __ldg(&b[tx * 8 + j]);

    #pragma unroll
    for (int i = 0; i < 8; i++) {
        int m = m0 + ty * 8 + i;
        if (m >= NN) continue;
        float* op = out + (size_t)m * 128 + tx * 8;
        float v[8];
        #pragma unroll
        for (int j2 = 0; j2 < 4; j2++) {
            float lo, hi;
            unpack2(z[i][j2], lo, hi);
            v[2 * j2 + 0] = fmaxf(lo + bv[2 * j2 + 0], 0.f) * third;
            v[2 * j2 + 1] = fmaxf(hi + bv[2 * j2 + 1], 0.f) * third;
        }
        if (!first) {
            float4 o0 = *(const float4*)(op);
            float4 o1 = *(const float4*)(op + 4);
            v[0] += o0.x; v[1] += o0.y; v[2] += o0.z; v[3] += o0.w;
            v[4] += o1.x; v[5] += o1.y; v[6] += o1.z; v[7] += o1.w;
        }
        *(float4*)(op)     = make_float4(v[0], v[1], v[2], v[3]);
        *(float4*)(op + 4) = make_float4(v[4], v[5], v[6], v[7]);
    }
}

// ---------------------------------------------------------------------------
// Launch. Inputs identified BY SIZE (robust to either metadata ordering):
//   12,800,000 -> x ; 1,600,000 -> (src,dst,w) triplets per relation ;
//   16,384 -> (Wself,Wneigh) pairs ; 128 -> biases in relation order.
// ---------------------------------------------------------------------------
extern "C" void kernel_launch(void* const* d_in, const int* in_sizes, int n_in,
                              void* d_out, int out_size)
{
    const float* x = nullptr;
    const int*   srcA[3] = {nullptr, nullptr, nullptr};
    const int*   dstA[3] = {nullptr, nullptr, nullptr};
    const float* wA[3]   = {nullptr, nullptr, nullptr};
    const float* WsA[3]  = {nullptr, nullptr, nullptr};
    const float* WnA[3]  = {nullptr, nullptr, nullptr};
    const float* bA[3]   = {nullptr, nullptr, nullptr};

    int nEdge = 0, nMat = 0, nBias = 0;
    for (int i = 0; i < n_in; i++) {
        int sz = in_sizes[i];
        if (sz == NN * DD) {
            x = (const float*)d_in[i];
        } else if (sz == EE) {
            int k = nEdge++;
            int rel = k / 3, kind = k % 3;
            if (rel < 3) {
                if (kind == 0)      srcA[rel] = (const int*)d_in[i];
                else if (kind == 1) dstA[rel] = (const int*)d_in[i];
                else                wA[rel]   = (const float*)d_in[i];
            }
        } else if (sz == DD * HH) {
            int k = nMat++;
            int rel = k / 2;
            if (rel < 3) {
                if ((k & 1) == 0) WsA[rel] = (const float*)d_in[i];
                else              WnA[rel] = (const float*)d_in[i];
            }
        } else if (sz == HH) {
            if (nBias < 3) bA[nBias++] = (const float*)d_in[i];
        }
    }

    float* out = (float*)d_out;

    int zeroBlocks = (NN * (DD / 4) + 255) / 256;
    int edgeBlocks = (EE + 7) / 8;
    int gemmBlocks = (NN + 127) / 128;

    for (int r = 0; r < 3; r++) {
        zero_kernel<<<zeroBlocks, 256>>>();
        edge_kernel<<<edgeBlocks, 256>>>(x, srcA[r], dstA[r], wA[r]);
        gemm_kernel<<<gemmBlocks, 256>>>(x, WsA[r], WnA[r], bA[r], out, r == 0);
    }
}